// round 17
// baseline (speedup 1.0000x reference)
#include <cuda_runtime.h>

// Problem dims
#define DM     1792           // D_MODEL
#define BBDIM  256            // BB
#define I_DIM  2048           // inner dim I
#define G_DIM  8192           // 4*I
#define GS4 ((size_t)I_DIM * I_DIM / 4)   // gate stride in float4

// Scratch state (allocation-free rule: __device__ globals)
__device__ float g_z[6 * G_DIM];      // gate preactivations (Wih part + biases)
__device__ float g_d[2][G_DIM];       // raw Whh·h dots, ping-pong by t&1
__device__ float g_cb[2][I_DIM];      // cell state, ping-pong by m&1

__device__ __forceinline__ float sigmoidf_(float x) {
    return 1.0f / (1.0f + expf(-x));
}
__device__ __forceinline__ float dot4(float4 a, float4 b) {
    return a.x * b.x + a.y * b.y + a.z * b.z + a.w * b.w;
}

// ---------------------------------------------------------------------------
// Quad-row warp dot (register double-buffer, distance-2 prefetch) — the
// proven 126.9us engine from R5/R6.
// ---------------------------------------------------------------------------
template <int NITER>
__device__ __forceinline__ void quad_dot(const float4* __restrict__ r0,
                                         const float4* __restrict__ r1,
                                         const float4* __restrict__ r2,
                                         const float4* __restrict__ r3,
                                         const float4* __restrict__ v4,
                                         int lane, float acc[4])
{
    float4 a0 = __ldcs(r0 + lane),      a1 = __ldcs(r1 + lane),
           a2 = __ldcs(r2 + lane),      a3 = __ldcs(r3 + lane);
    float4 b0 = __ldcs(r0 + lane + 32), b1 = __ldcs(r1 + lane + 32),
           b2 = __ldcs(r2 + lane + 32), b3 = __ldcs(r3 + lane + 32);

    acc[0] = acc[1] = acc[2] = acc[3] = 0.f;

#pragma unroll
    for (int k = 0; k < NITER; ++k) {
        float4 n0, n1, n2, n3;
        if (k + 2 < NITER) {
            n0 = __ldcs(r0 + lane + (k + 2) * 32);
            n1 = __ldcs(r1 + lane + (k + 2) * 32);
            n2 = __ldcs(r2 + lane + (k + 2) * 32);
            n3 = __ldcs(r3 + lane + (k + 2) * 32);
        }
        float4 h = v4[lane + k * 32];
        acc[0] += dot4(a0, h);
        acc[1] += dot4(a1, h);
        acc[2] += dot4(a2, h);
        acc[3] += dot4(a3, h);
        if (k + 1 < NITER) { a0 = b0; a1 = b1; a2 = b2; a3 = b3; }
        if (k + 2 < NITER) { b0 = n0; b1 = n1; b2 = n2; b3 = n3; }
    }
}

__device__ __forceinline__ void warp_sum4(float acc[4]) {
#pragma unroll
    for (int o = 16; o > 0; o >>= 1) {
        acc[0] += __shfl_xor_sync(0xffffffffu, acc[0], o);
        acc[1] += __shfl_xor_sync(0xffffffffu, acc[1], o);
        acc[2] += __shfl_xor_sync(0xffffffffu, acc[2], o);
        acc[3] += __shfl_xor_sync(0xffffffffu, acc[3], o);
    }
}

// ---------------------------------------------------------------------------
// Stage h_m into smem (computed elementwise — no materialized h buffer).
//   m == 0: gates = z0 only, c_prev = 0.
//   m >= 1: gates = z_m + d_m, c_prev = g_cb[(m-1)&1].
// Writes c_m to cw_g (if non-null; all blocks write identical values) and/or
// cw_s (smem, for the final step's epilogue).
// ---------------------------------------------------------------------------
__device__ __forceinline__ void stage_h(float* __restrict__ vsm, int m,
                                        float* __restrict__ cw_s, int tid)
{
    const float* z = g_z + (size_t)m * G_DIM;
    const float* d = (m >= 1) ? g_d[m & 1] : nullptr;
    const float* cp = (m >= 1) ? g_cb[(m - 1) & 1] : nullptr;
    float* cw = g_cb[m & 1];

    for (int k = tid; k < I_DIM; k += 128) {
        float gi = z[k];
        float gf = z[I_DIM + k];
        float gg = z[2 * I_DIM + k];
        float go = z[3 * I_DIM + k];
        if (d) {
            gi += d[k];
            gf += d[I_DIM + k];
            gg += d[2 * I_DIM + k];
            go += d[3 * I_DIM + k];
        }
        float c = sigmoidf_(gi) * tanhf(gg);
        if (cp) c += sigmoidf_(gf) * cp[k];
        vsm[k] = sigmoidf_(go) * tanhf(c);
        cw[k] = c;
        if (cw_s) cw_s[k] = c;
    }
}

// ---------------------------------------------------------------------------
// K0: z0, z1. 1024 blocks; block = 16 consecutive rows (warp quad = 4 rows).
// ---------------------------------------------------------------------------
__global__ void __launch_bounds__(128, 7) k0_kernel(
    const float* __restrict__ x, const float* __restrict__ y,
    const float* __restrict__ Wih5,
    const float* __restrict__ bih5, const float* __restrict__ bhh5)
{
    __shared__ float xs[I_DIM];

    const int t   = blockIdx.x >> 9;               // cell 0 or 1
    const int qb  = blockIdx.x & 511;
    const int tid = threadIdx.x;
    const int w    = tid >> 5;
    const int lane = tid & 31;

    for (int k = tid; k < DM; k += 128)    xs[k]      = x[t * DM + k];
    for (int k = tid; k < BBDIM; k += 128) xs[DM + k] = y[t * BBDIM + k];
    __syncthreads();

    const int r = ((qb << 2) + w) << 2;
    const float4* r0 = (const float4*)(Wih5 + ((size_t)t * G_DIM + r) * I_DIM);
    float acc[4];
    quad_dot<16>(r0, r0 + 512, r0 + 1024, r0 + 1536, (const float4*)xs, lane, acc);
    warp_sum4(acc);

    if (lane == 0) {
        const size_t zb = (size_t)t * G_DIM + r;
#pragma unroll
        for (int u = 0; u < 4; ++u)
            g_z[zb + u] = acc[u] + bih5[zb + u] + bhh5[zb + u];
    }
}

// ---------------------------------------------------------------------------
// Mid phase t (t = m+1): blocks [0,512) stream Whh(t) as CONSECUTIVE rows
// into raw dots g_d[t&1] (h_{t-1} staged by compute, c_{t-1} written).
// Blocks >= 512: z for cell t+1.
//   zmode 0: full Wih5[t+1] (512 z-blocks, K=2048)
//   zmode 1: final-cell slice of WihF (64 z-blocks, K=1792)
// ---------------------------------------------------------------------------
__global__ void __launch_bounds__(128, 7) mid_phase(
    const float* __restrict__ whh,   // Whh5[t]
    int m,                           // = t-1 (h index being staged)
    const float* __restrict__ wz,    // Wih for next cell
    const float* __restrict__ xvec,
    const float* __restrict__ yvec,  // null in zmode 1
    const float* __restrict__ bih,
    const float* __restrict__ bhh,
    int zout, int zmode)
{
    __shared__ float vsm[I_DIM];

    const int tid  = threadIdx.x;
    const int w    = tid >> 5;
    const int lane = tid & 31;

    if (blockIdx.x < 512) {
        // -------- Whh stream role: consecutive rows, raw dots --------
        stage_h(vsm, m, nullptr, tid);
        __syncthreads();

        const int r = ((blockIdx.x << 2) + w) << 2;   // 4 consecutive rows
        const float4* r0 = (const float4*)(whh + (size_t)r * I_DIM);
        float acc[4];
        quad_dot<16>(r0, r0 + 512, r0 + 1024, r0 + 1536,
                     (const float4*)vsm, lane, acc);
        warp_sum4(acc);

        float* dout = g_d[(m + 1) & 1];
        if (lane == 0) {
#pragma unroll
            for (int u = 0; u < 4; ++u) dout[r + u] = acc[u];
        }
    } else {
        // -------- z role --------
        const int q = ((blockIdx.x - 512) << 2) + w;  // warp-quad index

        if (zmode == 0) {
            for (int k = tid; k < DM; k += 128)    vsm[k]      = xvec[k];
            for (int k = tid; k < BBDIM; k += 128) vsm[DM + k] = yvec[k];
            __syncthreads();

            const int r = q << 2;
            const float4* r0 = (const float4*)(wz + (size_t)r * I_DIM);
            float acc[4];
            quad_dot<16>(r0, r0 + 512, r0 + 1024, r0 + 1536,
                         (const float4*)vsm, lane, acc);
            warp_sum4(acc);
            if (lane == 0) {
#pragma unroll
                for (int u = 0; u < 4; ++u)
                    g_z[zout + r + u] = acc[u] + bih[r + u] + bhh[r + u];
            }
        } else {
            for (int k = tid; k < DM; k += 128) vsm[k] = xvec[k];
            __syncthreads();

            const int rl = q << 2;                  // 0..1020
            const int g  = rl >> 8;
            const int jj = rl & 255;
            const int r  = g * I_DIM + DM + jj;     // 4 consecutive real rows
            const float4* r0 = (const float4*)(wz + (size_t)r * DM);
            float acc[4];
            quad_dot<14>(r0, r0 + 448, r0 + 896, r0 + 1344,
                         (const float4*)vsm, lane, acc);
            warp_sum4(acc);
            if (lane == 0) {
#pragma unroll
                for (int u = 0; u < 4; ++u)
                    g_z[zout + r + u] = acc[u] + bih[r + u] + bhh[r + u];
            }
        }
    }
}

// ---------------------------------------------------------------------------
// Final step: j in [1792,2048). 64 blocks; stage h4 (+c4 in smem), then warp
// owns one j, quad over the 4 gate rows of WhhF (strided — only 8.4 MB).
// ---------------------------------------------------------------------------
__global__ void __launch_bounds__(128, 7) final_step(
    const float* __restrict__ whhF,
    float* __restrict__ out)
{
    __shared__ float hs[I_DIM];
    __shared__ float cs[I_DIM];

    const int tid  = threadIdx.x;
    const int w    = tid >> 5;
    const int lane = tid & 31;

    stage_h(hs, 4, cs, tid);
    __syncthreads();

    const int j = DM + (blockIdx.x << 2) + w;      // 1792 .. 2047
    const float4* r0 = (const float4*)(whhF + (size_t)j * I_DIM);
    float acc[4];
    quad_dot<16>(r0, r0 + GS4, r0 + 2 * GS4, r0 + 3 * GS4,
                 (const float4*)hs, lane, acc);
    warp_sum4(acc);

    if (lane == 0) {
        const float* z = g_z + 5 * G_DIM;
        float gi = z[j]             + acc[0];
        float gf = z[I_DIM + j]     + acc[1];
        float gg = z[2 * I_DIM + j] + acc[2];
        float go = z[3 * I_DIM + j] + acc[3];
        float c  = sigmoidf_(gf) * cs[j] + sigmoidf_(gi) * tanhf(gg);
        float h  = sigmoidf_(go) * tanhf(c);
        out[j - DM] = h;
    }
}

// ---------------------------------------------------------------------------
extern "C" void kernel_launch(void* const* d_in, const int* in_sizes, int n_in,
                              void* d_out, int out_size)
{
    const float* x    = (const float*)d_in[0];
    const float* y    = (const float*)d_in[1];
    const float* Wih5 = (const float*)d_in[2];
    const float* Whh5 = (const float*)d_in[3];
    const float* bih5 = (const float*)d_in[4];
    const float* bhh5 = (const float*)d_in[5];
    const float* WihF = (const float*)d_in[6];
    const float* WhhF = (const float*)d_in[7];
    const float* bihF = (const float*)d_in[8];
    const float* bhhF = (const float*)d_in[9];
    float* out = (float*)d_out;

    (void)in_sizes; (void)n_in; (void)out_size;

    const size_t WSTEP = (size_t)G_DIM * I_DIM;

    // K0: z0, z1 (134 MB, fully parallel; Whh5[0] never read: h0=c0=0)
    k0_kernel<<<1024, 128>>>(x, y, Wih5, bih5, bhh5);

    // Phases 1..3: Whh(t) consecutive-row dots + z(t+1). 134 MB each.
    for (int t = 1; t <= 3; ++t) {
        mid_phase<<<1024, 128>>>(
            Whh5 + (size_t)t * WSTEP, t - 1,
            Wih5 + (size_t)(t + 1) * WSTEP,
            x + (t + 1) * DM, y + (t + 1) * BBDIM,
            bih5 + (size_t)(t + 1) * G_DIM, bhh5 + (size_t)(t + 1) * G_DIM,
            (t + 1) * G_DIM, /*zmode=*/0);
    }

    // Phase 4: Whh4 + final-cell z slice (67 + 7.3 MB)
    mid_phase<<<512 + 64, 128>>>(
        Whh5 + (size_t)4 * WSTEP, 3,
        WihF, x + 5 * DM, nullptr,
        bihF, bhhF, 5 * G_DIM, /*zmode=*/1);

    // Final: 256 outputs (8.4 MB), stages h4/c4 by compute
    final_step<<<64, 128>>>(WhhF, out);
}